// round 1
// baseline (speedup 1.0000x reference)
#include <cuda_runtime.h>
#include <math.h>

#define NS    16384
#define NSTEP 16383
#define TPB   1024
#define EPT   16

__global__ void __launch_bounds__(TPB, 1)
freqgen_kernel(const float* __restrict__ cond,
               const float* __restrict__ wn,
               const float* __restrict__ steps,
               float* __restrict__ out)
{
    __shared__ float warp_sums[32];

    const int row  = blockIdx.x;
    const int t    = threadIdx.x;
    const int lane = t & 31;
    const int wid  = t >> 5;
    const int base = t * EPT;

    const float* srow = steps + (long long)row * NSTEP;

    // ---- load my 16 (scaled) phase steps; last element of last thread is OOB ----
    float s[EPT];
#pragma unroll
    for (int k = 0; k < EPT; ++k) {
        int idx = base + k;
        float v = (idx < NSTEP) ? __ldg(srow + idx) : 0.0f;
        s[k] = __fmul_rn(0.01f, v);   // reference scales BEFORE cumsum
    }

    // ---- local inclusive scan ----
    float run = 0.0f;
#pragma unroll
    for (int k = 0; k < EPT; ++k) { run = __fadd_rn(run, s[k]); s[k] = run; }
    const float total = run;

    // ---- warp inclusive scan of per-thread totals ----
    float v = total;
#pragma unroll
    for (int o = 1; o < 32; o <<= 1) {
        float u = __shfl_up_sync(0xffffffffu, v, o);
        if (lane >= o) v += u;
    }
    if (lane == 31) warp_sums[wid] = v;
    __syncthreads();

    // ---- scan the 32 warp totals (warp 0) ----
    if (wid == 0) {
        float w = warp_sums[lane];
#pragma unroll
        for (int o = 1; o < 32; o <<= 1) {
            float u = __shfl_up_sync(0xffffffffu, w, o);
            if (lane >= o) w += u;
        }
        warp_sums[lane] = w;   // inclusive
    }
    __syncthreads();

    // exclusive prefix (sum of all scaled steps before my chunk)
    const float excl = (v - total) + (wid ? warp_sums[wid - 1] : 0.0f);

    // ---- per-row params ----
    const float amp = __ldg(cond + row * 3 + 0);
    const float f0  = __ldg(cond + row * 3 + 1);
    const float ph  = __ldg(cond + row * 3 + 2);
    // reference: ((2pi as f32) * f0) * n  -- keep exact rounding order, no FMA
    const float cf  = __fmul_rn(6.283185307179586f, f0);

    const double TWO_PI_D  = 6.283185307179586476925286766559;
    const double INV_2PI_D = 0.15915494309189533576888376337251;

    const float4* w4 = (const float4*)(wn  + (long long)row * NS) + t * 4;
    float4*       o4 = (float4*)      (out + (long long)row * NS) + t * 4;

    const float QD = 0.00784313725490196f;   // 2/255 rounded to f32
    const float QH = 0.00392156862745098f;   // 1/255 rounded to f32

#pragma unroll
    for (int c = 0; c < 4; ++c) {
        float4 wv = w4[c];
        float wa[4] = { wv.x, wv.y, wv.z, wv.w };
        float res[4];
#pragma unroll
        for (int j = 0; j < 4; ++j) {
            const int k = c * 4 + j;
            // phase_noise[n] = sum of scaled steps [0 .. n-1]
            float pn  = (k == 0) ? excl : __fadd_rn(excl, s[k - 1]);
            float nn  = (float)(base + k);
            // arg = ((cf*n) + ph) + pn  -- matches reference f32 rounding chain
            float arg = __fadd_rn(__fadd_rn(__fmul_rn(cf, nn), ph), pn);

            // reduce mod 2*pi in double (exact to ~1e-11), then fast-path cosf
            double ad = (double)arg;
            double q  = rint(ad * INV_2PI_D);
            float  r  = (float)fma(-q, TWO_PI_D, ad);
            float  xb = cosf(r);

            float x = __fadd_rn(__fmul_rn(amp, xb), __fmul_rn(0.1f, wa[j]));
            float y = __fadd_rn(__fmul_rn(QD, floorf(__fdiv_rn(x, QD))), QH);
            y = fminf(fmaxf(y, -1.0f), 1.0f);
            res[j] = y;
        }
        o4[c] = make_float4(res[0], res[1], res[2], res[3]);
    }
}

extern "C" void kernel_launch(void* const* d_in, const int* in_sizes, int n_in,
                              void* d_out, int out_size)
{
    const float* cond  = (const float*)d_in[0];
    const float* wn    = (const float*)d_in[1];
    const float* steps = (const float*)d_in[2];
    float* out = (float*)d_out;

    const int B = in_sizes[0] / 3;   // 4096
    freqgen_kernel<<<B, TPB>>>(cond, wn, steps, out);
}

// round 2
// speedup vs baseline: 2.8221x; 2.8221x over previous
#include <cuda_runtime.h>
#include <math.h>

#define NS    16384
#define NSTEP 16383
#define TPB   1024
#define EPT   16

__global__ void __launch_bounds__(TPB, 1)
freqgen_kernel(const float* __restrict__ cond,
               const float* __restrict__ wn,
               const float* __restrict__ steps,
               float* __restrict__ out)
{
    __shared__ float warp_sums[32];

    const int row  = blockIdx.x;
    const int t    = threadIdx.x;
    const int lane = t & 31;
    const int wid  = t >> 5;
    const int base = t * EPT;

    const float* srow = steps + (long long)row * NSTEP;

    // ---- load my 16 (scaled) phase steps; last element of last thread is OOB ----
    float s[EPT];
#pragma unroll
    for (int k = 0; k < EPT; ++k) {
        int idx = base + k;
        float v = (idx < NSTEP) ? __ldg(srow + idx) : 0.0f;
        s[k] = __fmul_rn(0.01f, v);   // reference scales BEFORE cumsum
    }

    // ---- local inclusive scan ----
    float run = 0.0f;
#pragma unroll
    for (int k = 0; k < EPT; ++k) { run = __fadd_rn(run, s[k]); s[k] = run; }
    const float total = run;

    // ---- warp inclusive scan of per-thread totals ----
    float v = total;
#pragma unroll
    for (int o = 1; o < 32; o <<= 1) {
        float u = __shfl_up_sync(0xffffffffu, v, o);
        if (lane >= o) v += u;
    }
    if (lane == 31) warp_sums[wid] = v;
    __syncthreads();

    // ---- scan the 32 warp totals (warp 0) ----
    if (wid == 0) {
        float w = warp_sums[lane];
#pragma unroll
        for (int o = 1; o < 32; o <<= 1) {
            float u = __shfl_up_sync(0xffffffffu, w, o);
            if (lane >= o) w += u;
        }
        warp_sums[lane] = w;   // inclusive
    }
    __syncthreads();

    // exclusive prefix (sum of all scaled steps before my chunk)
    const float excl = (v - total) + (wid ? warp_sums[wid - 1] : 0.0f);

    // ---- per-row params ----
    const float amp = __ldg(cond + row * 3 + 0);
    const float f0  = __ldg(cond + row * 3 + 1);
    const float ph  = __ldg(cond + row * 3 + 2);
    // reference: ((2pi as f32) * f0) -- keep exact f32 rounding, no FMA
    const float cf  = __fmul_rn(6.283185307179586f, f0);

    // Cody-Waite split of 2*pi in f32 (2 terms; 3rd term ~1e-14, q*C < 1e-9)
    const float INV_2PI = 0.15915494309189535f;
    const float PI2_A   = 6.28318548202514648f;   // f32(2*pi), slightly > 2*pi
    const float PI2_Bn  = 1.74845560007e-07f;     // -(2*pi - PI2_A) > 0

    const float4* w4 = (const float4*)(wn  + (long long)row * NS) + t * 4;
    float4*       o4 = (float4*)      (out + (long long)row * NS) + t * 4;

    const float QD = 0.0078431372549019608f;   // f32(2/255)
    const float QH = 0.0039215686274509804f;   // f32(1/255)

#pragma unroll
    for (int c = 0; c < 4; ++c) {
        float4 wv = w4[c];
        float wa[4] = { wv.x, wv.y, wv.z, wv.w };
        float res[4];
#pragma unroll
        for (int j = 0; j < 4; ++j) {
            const int k = c * 4 + j;
            // phase_noise[n] = sum of scaled steps [0 .. n-1]
            float pn  = (k == 0) ? excl : __fadd_rn(excl, s[k - 1]);
            float nn  = (float)(base + k);
            // arg = ((cf*n) + ph) + pn  -- matches reference f32 rounding chain
            float arg = __fadd_rn(__fadd_rn(__fmul_rn(cf, nn), ph), pn);

            // all-f32 Cody-Waite reduction mod 2*pi (error ~2e-7 rad)
            float q = rintf(__fmul_rn(arg, INV_2PI));
            float r = fmaf(q, -PI2_A, arg);
            r       = fmaf(q,  PI2_Bn, r);
            float xb = cosf(r);

            float x = __fadd_rn(__fmul_rn(amp, xb), __fmul_rn(0.1f, wa[j]));
            float y = __fadd_rn(__fmul_rn(QD, floorf(__fdiv_rn(x, QD))), QH);
            y = fminf(fmaxf(y, -1.0f), 1.0f);
            res[j] = y;
        }
        o4[c] = make_float4(res[0], res[1], res[2], res[3]);
    }
}

extern "C" void kernel_launch(void* const* d_in, const int* in_sizes, int n_in,
                              void* d_out, int out_size)
{
    const float* cond  = (const float*)d_in[0];
    const float* wn    = (const float*)d_in[1];
    const float* steps = (const float*)d_in[2];
    float* out = (float*)d_out;

    const int B = in_sizes[0] / 3;   // 4096
    freqgen_kernel<<<B, TPB>>>(cond, wn, steps, out);
}

// round 3
// speedup vs baseline: 4.4235x; 1.5674x over previous
#include <cuda_runtime.h>
#include <math.h>

#define NS    16384
#define NSTEP 16383
#define TPB   1024
#define EPT   16

// dynamic smem layout (floats):
//   [0, 16388)            pn2 : linear phase-noise, pn2[n] = phase_noise[n]
//   [16388, 16388+17408)  skew: 1024 rows x 17 (stride-17 kills bank conflicts)
#define PN2_WORDS  16388
#define SKEW_WORDS (1024 * 17)
#define SMEM_BYTES ((PN2_WORDS + SKEW_WORDS) * 4)

__global__ void __launch_bounds__(TPB, 1)
freqgen_kernel(const float* __restrict__ cond,
               const float* __restrict__ wn,
               const float* __restrict__ steps,
               float* __restrict__ out)
{
    extern __shared__ float sm[];
    float* pn2  = sm;
    float* skew = sm + PN2_WORDS;
    __shared__ float warp_sums[32];

    const int row  = blockIdx.x;
    const int t    = threadIdx.x;
    const int lane = t & 31;
    const int wid  = t >> 5;

    const float* srow = steps + (long long)row * NSTEP;

    // ---- Phase A: coalesced load of scaled steps into skewed smem ----
#pragma unroll
    for (int i = 0; i < 16; ++i) {
        int g = t + i * 1024;
        float v = (g < NSTEP) ? __fmul_rn(0.01f, __ldg(srow + g)) : 0.0f;
        skew[(g >> 4) * 17 + (g & 15)] = v;
    }
    __syncthreads();

    // ---- Phase B: scan. Thread t owns steps [t*16, t*16+16) via its skew row ----
    float s[EPT];
    {
        const float* myrow = skew + t * 17;   // stride 17: conflict-free
#pragma unroll
        for (int k = 0; k < EPT; ++k) s[k] = myrow[k];
    }
    float run = 0.0f;
#pragma unroll
    for (int k = 0; k < EPT; ++k) { run = __fadd_rn(run, s[k]); s[k] = run; }
    const float total = run;

    float v = total;
#pragma unroll
    for (int o = 1; o < 32; o <<= 1) {
        float u = __shfl_up_sync(0xffffffffu, v, o);
        if (lane >= o) v += u;
    }
    if (lane == 31) warp_sums[wid] = v;
    __syncthreads();
    if (wid == 0) {
        float w = warp_sums[lane];
#pragma unroll
        for (int o = 1; o < 32; o <<= 1) {
            float u = __shfl_up_sync(0xffffffffu, w, o);
            if (lane >= o) w += u;
        }
        warp_sums[lane] = w;   // inclusive
    }
    __syncthreads();
    const float excl = (v - total) + (wid ? warp_sums[wid - 1] : 0.0f);

    // write finished phase-noise values back into own skew row
    {
        float* myrow = skew + t * 17;
#pragma unroll
        for (int k = 0; k < EPT; ++k) myrow[k] = __fadd_rn(excl, s[k]);
    }
    __syncthreads();

    // ---- Relay: skew -> linear pn2 (both access patterns ~conflict-free) ----
#pragma unroll
    for (int i = 0; i < 16; ++i) {
        int g = t + i * 1024;
        pn2[g + 1] = skew[(g >> 4) * 17 + (g & 15)];   // pn2[n] for n = g+1
    }
    if (t == 0) pn2[0] = 0.0f;
    __syncthreads();

    // ---- Phase C: fully-coalesced compute. float4 group m = t + c*1024 ----
    const float amp = __ldg(cond + row * 3 + 0);
    const float f0  = __ldg(cond + row * 3 + 1);
    const float ph  = __ldg(cond + row * 3 + 2);
    const float cf  = __fmul_rn(6.283185307179586f, f0);  // ref f32 rounding

    const float INV_2PI = 0.15915494309189535f;
    const float PI2_A   = 6.28318548202514648f;   // f32(2*pi)
    const float PI2_Bn  = 1.74845560007e-07f;     // PI2_A - 2*pi (exact tail)
    const float QD      = 0.0078431372549019608f; // f32(2/255)
    const float QH      = 0.0039215686274509804f; // f32(1/255)

    const float4* w4 = (const float4*)(wn  + (long long)row * NS);
    float4*       o4 = (float4*)      (out + (long long)row * NS);
    const float4* p4 = (const float4*)pn2;

#pragma unroll
    for (int c = 0; c < 4; ++c) {
        const int m = t + c * 1024;
        float4 wv = w4[m];           // coalesced LDG.128
        float4 pv = p4[m];           // aligned LDS.128, conflict-free
        const float qf = (float)(4 * m);

        float wa[4]  = { wv.x, wv.y, wv.z, wv.w };
        float pnv[4] = { pv.x, pv.y, pv.z, pv.w };
        float res[4];
#pragma unroll
        for (int j = 0; j < 4; ++j) {
            float nn  = __fadd_rn(qf, (float)j);            // exact (< 2^24)
            float arg = __fadd_rn(__fadd_rn(__fmul_rn(cf, nn), ph), pnv[j]);

            // f32 Cody-Waite reduction mod 2*pi (err ~2e-7 rad), then MUFU cos
            float q = rintf(__fmul_rn(arg, INV_2PI));
            float r = fmaf(q, -PI2_A, arg);
            r       = fmaf(q,  PI2_Bn, r);
            float xb = __cosf(r);

            float x = __fadd_rn(__fmul_rn(amp, xb), __fmul_rn(0.1f, wa[j]));
            float y = fmaf(QD, floorf(__fmul_rn(x, 127.5f)), QH);
            y = fminf(fmaxf(y, -1.0f), 1.0f);
            res[j] = y;
        }
        o4[m] = make_float4(res[0], res[1], res[2], res[3]);  // coalesced STG.128
    }
}

extern "C" void kernel_launch(void* const* d_in, const int* in_sizes, int n_in,
                              void* d_out, int out_size)
{
    const float* cond  = (const float*)d_in[0];
    const float* wn    = (const float*)d_in[1];
    const float* steps = (const float*)d_in[2];
    float* out = (float*)d_out;

    cudaFuncSetAttribute(freqgen_kernel,
                         cudaFuncAttributeMaxDynamicSharedMemorySize, SMEM_BYTES);

    const int B = in_sizes[0] / 3;   // 4096
    freqgen_kernel<<<B, TPB, SMEM_BYTES>>>(cond, wn, steps, out);
}

// round 4
// speedup vs baseline: 5.8116x; 1.3138x over previous
#include <cuda_runtime.h>
#include <math.h>

#define NS    16384
#define NSTEP 16383
#define TPB   512
#define EPT   32
#define ROWL  33                       // 32 + 1 pad word per 32-group
#define SMEM_WORDS (TPB * ROWL)        // 16896 floats = 67584 B
#define SMEM_BYTES (SMEM_WORDS * 4)

__global__ void __launch_bounds__(TPB, 2)
freqgen_kernel(const float* __restrict__ cond,
               const float* __restrict__ wn,
               const float* __restrict__ steps,
               float* __restrict__ out)
{
    extern __shared__ float sm[];      // addr(n) = (n>>5)*33 + (n&31)
    __shared__ float warp_sums[32];

    const int row  = blockIdx.x;
    const int t    = threadIdx.x;
    const int lane = t & 31;
    const int wid  = t >> 5;           // 0..15

    const float* srow = steps + (long long)row * NSTEP;

    // ---- Phase A: coalesced load of scaled steps into padded smem ----
    // g = t + i*512 -> row = wid + 16*i, offset = lane  (conflict-free STS)
#pragma unroll
    for (int i = 0; i < EPT; ++i) {
        const int g = t + i * TPB;
        float v = (g < NSTEP) ? __fmul_rn(0.01f, __ldg(srow + g)) : 0.0f;
        sm[(wid + 16 * i) * ROWL + lane] = v;
    }
    __syncthreads();

    // ---- Phase B: in-place local inclusive scan of own row (banks t+k) ----
    float* myrow = sm + t * ROWL;
    float run = 0.0f;
#pragma unroll
    for (int k = 0; k < EPT; ++k) {
        run = __fadd_rn(run, myrow[k]);
        myrow[k] = run;                 // local inclusive cumsum
    }
    const float total = run;

    // block scan of per-thread totals (16 warps)
    float v = total;
#pragma unroll
    for (int o = 1; o < 32; o <<= 1) {
        float u = __shfl_up_sync(0xffffffffu, v, o);
        if (lane >= o) v += u;
    }
    if (lane == 31) warp_sums[wid] = v;
    __syncthreads();
    if (wid == 0) {
        float w = (lane < 16) ? warp_sums[lane] : 0.0f;
#pragma unroll
        for (int o = 1; o < 32; o <<= 1) {
            float u = __shfl_up_sync(0xffffffffu, w, o);
            if (lane >= o) w += u;
        }
        if (lane < 16) warp_sums[lane] = w;
    }
    __syncthreads();
    const float excl = (v - total) + (wid ? warp_sums[wid - 1] : 0.0f);

    // in-row shift: pn[32t+j] = excl + local[j-1], pn[32t] = excl.
    // Descending j: read offset j-1 before it is overwritten. Own row only.
#pragma unroll
    for (int j = EPT - 1; j >= 1; --j)
        myrow[j] = __fadd_rn(excl, myrow[j - 1]);
    myrow[0] = excl;                    // t==0: excl==0 -> pn[0]=0 exactly
    __syncthreads();

    // ---- Phase C: fully-coalesced streaming compute ----
    const float amp = __ldg(cond + row * 3 + 0);
    const float f0  = __ldg(cond + row * 3 + 1);
    const float ph  = __ldg(cond + row * 3 + 2);
    const float cf  = __fmul_rn(6.283185307179586f, f0);  // ref f32 rounding

    const float INV_2PI = 0.15915494309189535f;
    const float PI2_A   = 6.28318548202514648f;   // f32(2*pi)
    const float PI2_Bn  = 1.74845560007e-07f;     // PI2_A - 2*pi (exact tail)
    const float QD      = 0.0078431372549019608f; // f32(2/255)
    const float QH      = 0.0039215686274509804f; // f32(1/255)

    const float4* w4 = (const float4*)(wn  + (long long)row * NS);
    float4*       o4 = (float4*)      (out + (long long)row * NS);

#pragma unroll
    for (int c = 0; c < 8; ++c) {
        const int m = t + c * TPB;                  // float4 group index
        float4 wv = w4[m];                          // coalesced LDG.128
        const int a = (m >> 3) * ROWL + ((m & 7) << 2);
        const float qf = (float)(4 * m);

        float wa[4] = { wv.x, wv.y, wv.z, wv.w };
        float res[4];
#pragma unroll
        for (int j = 0; j < 4; ++j) {
            float pn  = sm[a + j];                  // conflict-free LDS.32
            float nn  = __fadd_rn(qf, (float)j);    // exact (< 2^24)
            float arg = __fadd_rn(__fadd_rn(__fmul_rn(cf, nn), ph), pn);

            // f32 Cody-Waite reduction mod 2*pi (err ~2e-7 rad), MUFU cos
            float q = rintf(__fmul_rn(arg, INV_2PI));
            float r = fmaf(q, -PI2_A, arg);
            r       = fmaf(q,  PI2_Bn, r);
            float xb = __cosf(r);

            float x = __fadd_rn(__fmul_rn(amp, xb), __fmul_rn(0.1f, wa[j]));
            float y = fmaf(QD, floorf(__fmul_rn(x, 127.5f)), QH);
            y = fminf(fmaxf(y, -1.0f), 1.0f);
            res[j] = y;
        }
        o4[m] = make_float4(res[0], res[1], res[2], res[3]);  // STG.128
    }
}

extern "C" void kernel_launch(void* const* d_in, const int* in_sizes, int n_in,
                              void* d_out, int out_size)
{
    const float* cond  = (const float*)d_in[0];
    const float* wn    = (const float*)d_in[1];
    const float* steps = (const float*)d_in[2];
    float* out = (float*)d_out;

    cudaFuncSetAttribute(freqgen_kernel,
                         cudaFuncAttributeMaxDynamicSharedMemorySize, SMEM_BYTES);

    const int B = in_sizes[0] / 3;   // 4096
    freqgen_kernel<<<B, TPB, SMEM_BYTES>>>(cond, wn, steps, out);
}